// round 16
// baseline (speedup 1.0000x reference)
#include <cuda_runtime.h>
#include <math.h>

#define BB 1024
#define SS 64
#define DD 256
#define CHN 1024
#define NCH 16   // samples per chunk (k_hidden)
#define NHID_BLOCKS (64 * 2 * 2)

typedef unsigned long long u64;

// scratch (device globals; no allocation allowed; zero-initialized statics)
__device__ int   g_cnt[SS];               // per-scene sample counts
__device__ int   g_done;                  // k_hidden completion counter
__device__ int   g_list[SS][BB];          // per-scene sample lists (global ordering)
__device__ __align__(16) float g_desc[2][BB][DD];   // gathered descriptors (t, rot)

// ---- packed f32x2 helpers (Blackwell) --------------------------------------
__device__ __forceinline__ u64 dup2(float w) {
    unsigned u = __float_as_uint(w);
    u64 r; asm("mov.b64 %0, {%1, %2};" : "=l"(r) : "r"(u), "r"(u)); return r;
}
__device__ __forceinline__ u64 pack2(float lo, float hi) {
    u64 r; asm("mov.b64 %0, {%1, %2};" : "=l"(r) : "r"(__float_as_uint(lo)), "r"(__float_as_uint(hi)));
    return r;
}
__device__ __forceinline__ float2 unpk2(u64 v) {
    unsigned lo, hi; asm("mov.b64 {%0, %1}, %2;" : "=r"(lo), "=r"(hi) : "l"(v));
    return make_float2(__uint_as_float(lo), __uint_as_float(hi));
}
__device__ __forceinline__ u64 ffma2(u64 a, u64 b, u64 c) {
    u64 d; asm("fma.rn.f32x2 %0, %1, %2, %3;" : "=l"(d) : "l"(a), "l"(b), "l"(c));
    return d;
}

// ---------------------------------------------------------------------------
// K1: fused logits + log_softmax + argmax + scene-list append + gather + bias.
// One block per sample, 1024 threads; warp w computes scene rows 2w, 2w+1.
// g_cnt was zeroed by the previous replay's k_hidden (or static init, run 1).
// ---------------------------------------------------------------------------
__global__ void __launch_bounds__(1024) k_front(
        const float* __restrict__ t, const float* __restrict__ r,
        const float* __restrict__ Wsc, const float* __restrict__ bsc,
        const float* __restrict__ bto, const float* __restrict__ bro,
        float* __restrict__ logd, float* __restrict__ pose) {
    int b    = blockIdx.x;
    int tid  = threadIdx.x;
    int wid  = tid >> 5;
    int lane = tid & 31;
    __shared__ float l[SS];
    __shared__ float lse;
    __shared__ int   am;

    {   // logits for scene rows s0, s0+1 (2 rows per warp, W regs shared)
        int s0 = wid * 2;
        const float4* t40 = (const float4*)(t + ((size_t)b * SS + s0) * DD);
        const float4* r40 = (const float4*)(r + ((size_t)b * SS + s0) * DD);
        const float4* t41 = t40 + DD / 4;
        const float4* r41 = r40 + DD / 4;
        const float4* W4  = (const float4*)Wsc;
        float acc0 = 0.f, acc1 = 0.f;
#pragma unroll
        for (int j = 0; j < 2; j++) {
            int k = j * 32 + lane;
            float4 wa = W4[k];
            float4 wb = W4[64 + k];
            float4 a0 = t40[k], b0 = r40[k];
            float4 a1 = t41[k], b1 = r41[k];
            acc0 = fmaf(a0.x, wa.x, acc0); acc0 = fmaf(a0.y, wa.y, acc0);
            acc0 = fmaf(a0.z, wa.z, acc0); acc0 = fmaf(a0.w, wa.w, acc0);
            acc0 = fmaf(b0.x, wb.x, acc0); acc0 = fmaf(b0.y, wb.y, acc0);
            acc0 = fmaf(b0.z, wb.z, acc0); acc0 = fmaf(b0.w, wb.w, acc0);
            acc1 = fmaf(a1.x, wa.x, acc1); acc1 = fmaf(a1.y, wa.y, acc1);
            acc1 = fmaf(a1.z, wa.z, acc1); acc1 = fmaf(a1.w, wa.w, acc1);
            acc1 = fmaf(b1.x, wb.x, acc1); acc1 = fmaf(b1.y, wb.y, acc1);
            acc1 = fmaf(b1.z, wb.z, acc1); acc1 = fmaf(b1.w, wb.w, acc1);
        }
#pragma unroll
        for (int o = 16; o; o >>= 1) {
            acc0 += __shfl_xor_sync(0xFFFFFFFFu, acc0, o);
            acc1 += __shfl_xor_sync(0xFFFFFFFFu, acc1, o);
        }
        if (lane == 0) {
            float bb = bsc[0];
            l[s0]     = acc0 + bb;
            l[s0 + 1] = acc1 + bb;
        }
    }
    __syncthreads();

    if (wid == 0) {   // warp-parallel max/argmax/lse over 64 values
        float v0 = l[lane], v1 = l[lane + 32];
        float m; int a;
        if (v1 > v0) { m = v1; a = lane + 32; } else { m = v0; a = lane; }
#pragma unroll
        for (int o = 16; o; o >>= 1) {
            float mo = __shfl_down_sync(0xFFFFFFFFu, m, o);
            int   ao = __shfl_down_sync(0xFFFFFFFFu, a, o);
            if (mo > m || (mo == m && ao < a)) { m = mo; a = ao; }
        }
        m = __shfl_sync(0xFFFFFFFFu, m, 0);
        a = __shfl_sync(0xFFFFFFFFu, a, 0);
        float s = expf(v0 - m) + expf(v1 - m);
#pragma unroll
        for (int o = 16; o; o >>= 1) s += __shfl_xor_sync(0xFFFFFFFFu, s, o);
        if (lane == 0) {
            lse = m + logf(s);
            am  = a;
            int p = atomicAdd(&g_cnt[a], 1);   // single global ordering
            g_list[a][p] = b;
        }
    }
    __syncthreads();
    int a = am;
    if (tid < SS) {
        logd[b * SS + tid] = l[tid] - lse;
    } else if (tid < 128) {
        int i = tid - 64;
        ((float4*)g_desc[0][b])[i] =
            ((const float4*)(t + ((size_t)b * SS + a) * DD))[i];
    } else if (tid < 192) {
        int i = tid - 128;
        ((float4*)g_desc[1][b])[i] =
            ((const float4*)(r + ((size_t)b * SS + a) * DD))[i];
    } else if (tid < 199) {
        int o = tid - 192;                     // pose bias init
        pose[b * 7 + o] = (o < 3) ? bto[a * 3 + o] : bro[a * 4 + (o - 3)];
    }
}

// ---------------------------------------------------------------------------
// K2: fused expert hidden layer + gelu + output projection.
// grid = (64 scenes, 2 heads, 2 jc) scene-major, 512 threads (16 warps/block).
// Thread owns 2 consecutive channels (LDG.64 weights) x 16 samples
// (8 f32x2 pairs) -> 16 u64 accumulators (low regs -> 2 blocks/SM).
// Sample pairs pre-packed as u64 in smem; 4x LDS.128 broadcast per d.
// Last-finishing block zeroes g_cnt for the next replay (done-counter).
// ---------------------------------------------------------------------------
__global__ void __launch_bounds__(512, 2) k_hidden(
        const float* __restrict__ Wth, const float* __restrict__ bth,
        const float* __restrict__ Wto,
        const float* __restrict__ Wrh, const float* __restrict__ brh,
        const float* __restrict__ Wro,
        float* __restrict__ pose) {
    int scene = blockIdx.x;            // 0..63
    int head  = blockIdx.y;            // 0..1
    int jc    = blockIdx.z;            // chunk slot 0..1
    int tid   = threadIdx.x;
    int lane  = tid & 31;

    int cnt = g_cnt[scene];

    __shared__ __align__(16) u64 gs2[DD][10];   // 8 packed pairs + pad (80B rows)
    __shared__ float part[NCH][4];

    if (jc * NCH < cnt) {              // block-uniform condition
        const int* list = g_list[scene];
        const float* W    = head ? Wrh : Wth;
        const float* bias = head ? brh : bth;
        const float* Wo   = head ? Wro : Wto;
        const int    NO   = head ? 4 : 3;
        const int    ooff = head ? 3 : 0;

        int ch = tid * 2;                              // 2 consecutive channels
        const float* Ws = W + (size_t)scene * DD * CHN;

        for (int c0 = jc * NCH; c0 < cnt; c0 += 2 * NCH) {
            int nc = min(NCH, cnt - c0);
            __syncthreads();    // protect gs2/part reuse across chunks
            {
                const float* gd = &g_desc[head][0][0];
                int d  = tid & 255;                    // row
                int ph = (tid >> 8) * 4;               // pair range 0-3 or 4-7
#pragma unroll
                for (int p = 0; p < 4; p++) {
                    int n0 = 2 * (ph + p), n1 = n0 + 1;
                    float v0 = (n0 < nc) ? gd[(size_t)list[c0 + n0] * DD + d] : 0.f;
                    float v1 = (n1 < nc) ? gd[(size_t)list[c0 + n1] * DD + d] : 0.f;
                    gs2[d][ph + p] = pack2(v0, v1);
                }
            }
            if (tid < NCH * 4) part[tid >> 2][tid & 3] = 0.f;
            __syncthreads();

            u64 acc[2][8];      // [channel][sample-pair]
#pragma unroll
            for (int c = 0; c < 2; c++)
#pragma unroll
                for (int p = 0; p < 8; p++) acc[c][p] = 0ull;

#pragma unroll 4
            for (int d = 0; d < DD; d++) {
                float2 wv = *(const float2*)&Ws[(size_t)d * CHN + ch];
                u64 w0 = dup2(wv.x);
                u64 w1 = dup2(wv.y);
                ulonglong2 ga = *(const ulonglong2*)&gs2[d][0];  // pairs 0,1
                ulonglong2 gb = *(const ulonglong2*)&gs2[d][2];  // pairs 2,3
                ulonglong2 gc = *(const ulonglong2*)&gs2[d][4];  // pairs 4,5
                ulonglong2 ge = *(const ulonglong2*)&gs2[d][6];  // pairs 6,7
                u64 gp[8] = {ga.x, ga.y, gb.x, gb.y, gc.x, gc.y, ge.x, ge.y};
#pragma unroll
                for (int p = 0; p < 8; p++) {
                    acc[0][p] = ffma2(gp[p], w0, acc[0][p]);
                    acc[1][p] = ffma2(gp[p], w1, acc[1][p]);
                }
            }

            // epilogue (loads here to keep main-loop register pressure low)
            float2 bv = *(const float2*)&bias[(size_t)scene * CHN + ch];
            float wo[2][4];
#pragma unroll
            for (int c = 0; c < 2; c++)
#pragma unroll
                for (int o = 0; o < 4; o++)
                    wo[c][o] = (o < NO) ? Wo[((size_t)scene * CHN + ch + c) * NO + o] : 0.f;

#pragma unroll
            for (int p = 0; p < 8; p++) {
                float2 x0 = unpk2(acc[0][p]);
                float2 x1 = unpk2(acc[1][p]);
#pragma unroll
                for (int q = 0; q < 2; q++) {
                    int n = 2 * p + q;
                    if (n < nc) {                       // warp-uniform
                        float h0x = (q ? x0.y : x0.x) + bv.x;
                        float h1x = (q ? x1.y : x1.x) + bv.y;
                        float h0 = 0.5f * h0x * (1.0f + erff(h0x * 0.70710678118654752f));
                        float h1 = 0.5f * h1x * (1.0f + erff(h1x * 0.70710678118654752f));
                        float pv[4];
#pragma unroll
                        for (int o = 0; o < 4; o++) pv[o] = h0 * wo[0][o] + h1 * wo[1][o];
#pragma unroll
                        for (int off = 16; off; off >>= 1) {
                            pv[0] += __shfl_down_sync(0xFFFFFFFFu, pv[0], off);
                            pv[1] += __shfl_down_sync(0xFFFFFFFFu, pv[1], off);
                            pv[2] += __shfl_down_sync(0xFFFFFFFFu, pv[2], off);
                            pv[3] += __shfl_down_sync(0xFFFFFFFFu, pv[3], off);
                        }
                        if (lane == 0) {
                            atomicAdd(&part[n][0], pv[0]);
                            atomicAdd(&part[n][1], pv[1]);
                            atomicAdd(&part[n][2], pv[2]);
                            atomicAdd(&part[n][3], pv[3]);
                        }
                    }
                }
            }
            __syncthreads();
            if (tid < NCH * 4) {
                int n = tid >> 2, o = tid & 3;
                if (n < nc && o < NO)
                    atomicAdd(&pose[(size_t)list[c0 + n] * 7 + ooff + o], part[n][o]);
            }
        }
    }

    // done-counter: last block of the launch zeroes g_cnt for the next replay
    __syncthreads();
    if (tid == 0) {
        __threadfence();
        int v = atomicAdd(&g_done, 1);
        if (v == NHID_BLOCKS - 1) {
#pragma unroll
            for (int s = 0; s < SS; s++) g_cnt[s] = 0;
            __threadfence();
            g_done = 0;
        }
    }
}

// ---------------------------------------------------------------------------
extern "C" void kernel_launch(void* const* d_in, const int* in_sizes, int n_in,
                              void* d_out, int out_size) {
    const float* t   = (const float*)d_in[0];
    const float* r   = (const float*)d_in[1];
    const float* Wsc = (const float*)d_in[2];
    const float* bsc = (const float*)d_in[3];
    const float* Wth = (const float*)d_in[4];
    const float* bth = (const float*)d_in[5];
    const float* Wto = (const float*)d_in[6];
    const float* bto = (const float*)d_in[7];
    const float* Wrh = (const float*)d_in[8];
    const float* brh = (const float*)d_in[9];
    const float* Wro = (const float*)d_in[10];
    const float* bro = (const float*)d_in[11];

    float* out  = (float*)d_out;
    float* pose = out;             // [B,7]
    float* logd = out + BB * 7;    // [B,S]

    k_front<<<BB, 1024>>>(t, r, Wsc, bsc, bto, bro, logd, pose);
    dim3 gh(64, 2, 2);
    k_hidden<<<gh, 512>>>(Wth, bth, Wto, Wrh, brh, Wro, pose);
}

// round 17
// speedup vs baseline: 1.2068x; 1.2068x over previous
#include <cuda_runtime.h>
#include <math.h>

#define BB 1024
#define SS 64
#define DD 256
#define CHN 1024
#define NCH 8    // samples per chunk (k_hidden)
#define NHID_BLOCKS (64 * 2 * 4)
#define KC 8     // weight pipeline rows per stage
#define NBLK (DD / KC)

typedef unsigned long long u64;

// scratch (device globals; no allocation allowed; zero-initialized statics)
__device__ int   g_cnt[SS];               // per-scene sample counts
__device__ int   g_done;                  // k_hidden completion counter
__device__ int   g_list[SS][BB];          // per-scene sample lists (global ordering)
__device__ __align__(16) float g_desc[2][BB][DD];   // gathered descriptors (t, rot)

// ---- packed f32x2 helpers (Blackwell) --------------------------------------
__device__ __forceinline__ u64 dup2(float w) {
    unsigned u = __float_as_uint(w);
    u64 r; asm("mov.b64 %0, {%1, %2};" : "=l"(r) : "r"(u), "r"(u)); return r;
}
__device__ __forceinline__ float2 unpk2(u64 v) {
    unsigned lo, hi; asm("mov.b64 {%0, %1}, %2;" : "=r"(lo), "=r"(hi) : "l"(v));
    return make_float2(__uint_as_float(lo), __uint_as_float(hi));
}
__device__ __forceinline__ u64 ffma2(u64 a, u64 b, u64 c) {
    u64 d; asm("fma.rn.f32x2 %0, %1, %2, %3;" : "=l"(d) : "l"(a), "l"(b), "l"(c));
    return d;
}
__device__ __forceinline__ void cp_async16(unsigned saddr, const void* gptr) {
    asm volatile("cp.async.cg.shared.global [%0], [%1], 16;" :: "r"(saddr), "l"(gptr));
}
__device__ __forceinline__ void cp_commit() {
    asm volatile("cp.async.commit_group;" ::: "memory");
}
__device__ __forceinline__ void cp_wait1() {
    asm volatile("cp.async.wait_group 1;" ::: "memory");
}
__device__ __forceinline__ void cp_wait0() {
    asm volatile("cp.async.wait_group 0;" ::: "memory");
}

// ---------------------------------------------------------------------------
// K1: fused logits + log_softmax + argmax + scene-list append + gather + bias.
// One block per sample, 1024 threads; warp w computes scene rows 2w, 2w+1.
// g_cnt was zeroed by the previous replay's k_hidden (or static init, run 1).
// ---------------------------------------------------------------------------
__global__ void __launch_bounds__(1024) k_front(
        const float* __restrict__ t, const float* __restrict__ r,
        const float* __restrict__ Wsc, const float* __restrict__ bsc,
        const float* __restrict__ bto, const float* __restrict__ bro,
        float* __restrict__ logd, float* __restrict__ pose) {
    int b    = blockIdx.x;
    int tid  = threadIdx.x;
    int wid  = tid >> 5;
    int lane = tid & 31;
    __shared__ float l[SS];
    __shared__ float lse;
    __shared__ int   am;

    {   // logits for scene rows s0, s0+1 (2 rows per warp, W regs shared)
        int s0 = wid * 2;
        const float4* t40 = (const float4*)(t + ((size_t)b * SS + s0) * DD);
        const float4* r40 = (const float4*)(r + ((size_t)b * SS + s0) * DD);
        const float4* t41 = t40 + DD / 4;
        const float4* r41 = r40 + DD / 4;
        const float4* W4  = (const float4*)Wsc;
        float acc0 = 0.f, acc1 = 0.f;
#pragma unroll
        for (int j = 0; j < 2; j++) {
            int k = j * 32 + lane;
            float4 wa = W4[k];
            float4 wb = W4[64 + k];
            float4 a0 = t40[k], b0 = r40[k];
            float4 a1 = t41[k], b1 = r41[k];
            acc0 = fmaf(a0.x, wa.x, acc0); acc0 = fmaf(a0.y, wa.y, acc0);
            acc0 = fmaf(a0.z, wa.z, acc0); acc0 = fmaf(a0.w, wa.w, acc0);
            acc0 = fmaf(b0.x, wb.x, acc0); acc0 = fmaf(b0.y, wb.y, acc0);
            acc0 = fmaf(b0.z, wb.z, acc0); acc0 = fmaf(b0.w, wb.w, acc0);
            acc1 = fmaf(a1.x, wa.x, acc1); acc1 = fmaf(a1.y, wa.y, acc1);
            acc1 = fmaf(a1.z, wa.z, acc1); acc1 = fmaf(a1.w, wa.w, acc1);
            acc1 = fmaf(b1.x, wb.x, acc1); acc1 = fmaf(b1.y, wb.y, acc1);
            acc1 = fmaf(b1.z, wb.z, acc1); acc1 = fmaf(b1.w, wb.w, acc1);
        }
#pragma unroll
        for (int o = 16; o; o >>= 1) {
            acc0 += __shfl_xor_sync(0xFFFFFFFFu, acc0, o);
            acc1 += __shfl_xor_sync(0xFFFFFFFFu, acc1, o);
        }
        if (lane == 0) {
            float bb = bsc[0];
            l[s0]     = acc0 + bb;
            l[s0 + 1] = acc1 + bb;
        }
    }
    __syncthreads();

    if (wid == 0) {   // warp-parallel max/argmax/lse over 64 values
        float v0 = l[lane], v1 = l[lane + 32];
        float m; int a;
        if (v1 > v0) { m = v1; a = lane + 32; } else { m = v0; a = lane; }
#pragma unroll
        for (int o = 16; o; o >>= 1) {
            float mo = __shfl_down_sync(0xFFFFFFFFu, m, o);
            int   ao = __shfl_down_sync(0xFFFFFFFFu, a, o);
            if (mo > m || (mo == m && ao < a)) { m = mo; a = ao; }
        }
        m = __shfl_sync(0xFFFFFFFFu, m, 0);
        a = __shfl_sync(0xFFFFFFFFu, a, 0);
        float s = expf(v0 - m) + expf(v1 - m);
#pragma unroll
        for (int o = 16; o; o >>= 1) s += __shfl_xor_sync(0xFFFFFFFFu, s, o);
        if (lane == 0) {
            lse = m + logf(s);
            am  = a;
            int p = atomicAdd(&g_cnt[a], 1);   // single global ordering
            g_list[a][p] = b;
        }
    }
    __syncthreads();
    int a = am;
    if (tid < SS) {
        logd[b * SS + tid] = l[tid] - lse;
    } else if (tid < 128) {
        int i = tid - 64;
        ((float4*)g_desc[0][b])[i] =
            ((const float4*)(t + ((size_t)b * SS + a) * DD))[i];
    } else if (tid < 192) {
        int i = tid - 128;
        ((float4*)g_desc[1][b])[i] =
            ((const float4*)(r + ((size_t)b * SS + a) * DD))[i];
    } else if (tid < 199) {
        int o = tid - 192;                     // pose bias init
        pose[b * 7 + o] = (o < 3) ? bto[a * 3 + o] : bro[a * 4 + (o - 3)];
    }
}

// ---------------------------------------------------------------------------
// K2: fused expert hidden layer + gelu + projection, cp.async weight pipeline.
// grid = (64 scenes, 2 heads, 4 jc) scene-major, 256 threads. Thread owns 4
// CONSECUTIVE channels; weights staged through double-buffered smem via
// cp.async (in-flight loads cost no registers). Each thread cp.asyncs and
// consumes ONLY its own 16B/row slots -> no __syncthreads in pipeline loop.
// Dynamic smem: wbuf[2][KC][1024]f (64KB) + gs[DD][10]f (10KB) + part (128B).
// Last-finishing block zeroes g_cnt for the next replay (done-counter).
// ---------------------------------------------------------------------------
__global__ void __launch_bounds__(256, 3) k_hidden(
        const float* __restrict__ Wth, const float* __restrict__ bth,
        const float* __restrict__ Wto,
        const float* __restrict__ Wrh, const float* __restrict__ brh,
        const float* __restrict__ Wro,
        float* __restrict__ pose) {
    int scene = blockIdx.x;            // 0..63
    int head  = blockIdx.y;            // 0..1
    int jc    = blockIdx.z;            // chunk slot 0..3
    int tid   = threadIdx.x;
    int lane  = tid & 31;

    extern __shared__ __align__(16) char smem[];
    float* wb = (float*)smem;                                  // [2][KC][1024]
    float (*gs)[NCH + 2] = (float(*)[NCH + 2])(smem + 2 * KC * CHN * 4);
    float (*part)[4]     = (float(*)[4])(smem + 2 * KC * CHN * 4 + DD * (NCH + 2) * 4);

    int cnt = g_cnt[scene];

    if (jc * NCH < cnt) {              // block-uniform condition
        const int* list = g_list[scene];
        const float* W    = head ? Wrh : Wth;
        const float* bias = head ? brh : bth;
        const float* Wo   = head ? Wro : Wto;
        const int    NO   = head ? 4 : 3;
        const int    ooff = head ? 3 : 0;

        int ch = tid * 4;                              // 4 consecutive channels
        const float* Ws = W + (size_t)scene * DD * CHN;
        unsigned wsm = (unsigned)__cvta_generic_to_shared(wb) + (unsigned)tid * 16u;

        for (int c0 = jc * NCH; c0 < cnt; c0 += 4 * NCH) {
            int nc = min(NCH, cnt - c0);
            __syncthreads();    // protect gs/part reuse across chunks
            {
                const float* gd = &g_desc[head][0][0];
#pragma unroll
                for (int n = 0; n < NCH; n++) {
                    float v = (n < nc) ? gd[(size_t)list[c0 + n] * DD + tid] : 0.f;
                    gs[tid][n] = v;
                }
            }
            if (tid < NCH * 4) part[tid >> 2][tid & 3] = 0.f;
            __syncthreads();

            u64 acc[4][4];      // [channel][sample-pair]
#pragma unroll
            for (int c = 0; c < 4; c++)
#pragma unroll
                for (int p = 0; p < 4; p++) acc[c][p] = 0ull;

            // ---- weight pipeline: prologue fills stage 0 ----
#pragma unroll
            for (int rr = 0; rr < KC; rr++)
                cp_async16(wsm + rr * (CHN * 4), Ws + (size_t)rr * CHN + ch);
            cp_commit();

            for (int blk = 0; blk < NBLK; blk++) {
                int stage = blk & 1;
                if (blk + 1 < NBLK) {   // issue next stage before consuming
                    unsigned dst = wsm + ((blk + 1) & 1) * (KC * CHN * 4);
                    const float* src = Ws + (size_t)(blk + 1) * KC * CHN + ch;
#pragma unroll
                    for (int rr = 0; rr < KC; rr++)
                        cp_async16(dst + rr * (CHN * 4), src + (size_t)rr * CHN);
                    cp_commit();
                    cp_wait1();         // current stage's group complete
                } else {
                    cp_wait0();
                }
                const float* wrow = wb + stage * (KC * CHN) + ch;
#pragma unroll
                for (int rr = 0; rr < KC; rr++) {
                    int d = blk * KC + rr;
                    float4 wv = *(const float4*)(wrow + rr * CHN);
                    u64 wd[4] = {dup2(wv.x), dup2(wv.y), dup2(wv.z), dup2(wv.w)};
                    const u64* grow = (const u64*)&gs[d][0];
#pragma unroll
                    for (int p = 0; p < 4; p++) {
                        u64 gp = grow[p];
#pragma unroll
                        for (int c = 0; c < 4; c++)
                            acc[c][p] = ffma2(gp, wd[c], acc[c][p]);
                    }
                }
            }

            // epilogue (loads here to keep main-loop register pressure low)
            float4 bv = *(const float4*)&bias[(size_t)scene * CHN + ch];
            float bvs[4] = {bv.x, bv.y, bv.z, bv.w};
            float wo[4][4];
#pragma unroll
            for (int c = 0; c < 4; c++)
#pragma unroll
                for (int o = 0; o < 4; o++)
                    wo[c][o] = (o < NO) ? Wo[((size_t)scene * CHN + ch + c) * NO + o] : 0.f;

#pragma unroll
            for (int p = 0; p < 4; p++) {
                float2 xs[4];
#pragma unroll
                for (int c = 0; c < 4; c++) xs[c] = unpk2(acc[c][p]);
#pragma unroll
                for (int q = 0; q < 2; q++) {
                    int n = 2 * p + q;
                    if (n < nc) {                       // warp-uniform
                        float pv[4] = {0.f, 0.f, 0.f, 0.f};
#pragma unroll
                        for (int c = 0; c < 4; c++) {
                            float x = (q ? xs[c].y : xs[c].x) + bvs[c];
                            float h = 0.5f * x * (1.0f + erff(x * 0.70710678118654752f));
#pragma unroll
                            for (int o = 0; o < 4; o++) pv[o] = fmaf(h, wo[c][o], pv[o]);
                        }
#pragma unroll
                        for (int off = 16; off; off >>= 1) {
                            pv[0] += __shfl_down_sync(0xFFFFFFFFu, pv[0], off);
                            pv[1] += __shfl_down_sync(0xFFFFFFFFu, pv[1], off);
                            pv[2] += __shfl_down_sync(0xFFFFFFFFu, pv[2], off);
                            pv[3] += __shfl_down_sync(0xFFFFFFFFu, pv[3], off);
                        }
                        if (lane == 0) {
                            atomicAdd(&part[n][0], pv[0]);
                            atomicAdd(&part[n][1], pv[1]);
                            atomicAdd(&part[n][2], pv[2]);
                            atomicAdd(&part[n][3], pv[3]);
                        }
                    }
                }
            }
            __syncthreads();
            if (tid < NCH * 4) {
                int n = tid >> 2, o = tid & 3;
                if (n < nc && o < NO)
                    atomicAdd(&pose[(size_t)list[c0 + n] * 7 + ooff + o], part[n][o]);
            }
        }
    }

    // done-counter: last block of the launch zeroes g_cnt for the next replay
    __syncthreads();
    if (tid == 0) {
        __threadfence();
        int v = atomicAdd(&g_done, 1);
        if (v == NHID_BLOCKS - 1) {
#pragma unroll
            for (int s = 0; s < SS; s++) g_cnt[s] = 0;
            __threadfence();
            g_done = 0;
        }
    }
}

// ---------------------------------------------------------------------------
extern "C" void kernel_launch(void* const* d_in, const int* in_sizes, int n_in,
                              void* d_out, int out_size) {
    const float* t   = (const float*)d_in[0];
    const float* r   = (const float*)d_in[1];
    const float* Wsc = (const float*)d_in[2];
    const float* bsc = (const float*)d_in[3];
    const float* Wth = (const float*)d_in[4];
    const float* bth = (const float*)d_in[5];
    const float* Wto = (const float*)d_in[6];
    const float* bto = (const float*)d_in[7];
    const float* Wrh = (const float*)d_in[8];
    const float* brh = (const float*)d_in[9];
    const float* Wro = (const float*)d_in[10];
    const float* bro = (const float*)d_in[11];

    float* out  = (float*)d_out;
    float* pose = out;             // [B,7]
    float* logd = out + BB * 7;    // [B,S]

    const int shmem = 2 * KC * CHN * 4 + DD * (NCH + 2) * 4 + NCH * 4 * 4;
    cudaFuncSetAttribute(k_hidden, cudaFuncAttributeMaxDynamicSharedMemorySize, shmem);

    k_front<<<BB, 1024>>>(t, r, Wsc, bsc, bto, bro, logd, pose);
    dim3 gh(64, 2, 4);
    k_hidden<<<gh, 256, shmem>>>(Wth, bth, Wto, Wrh, brh, Wro, pose);
}